// round 1
// baseline (speedup 1.0000x reference)
#include <cuda_runtime.h>
#include <math.h>

#define NB 8192
#define NH 2048
#define ND 2048
#define NR 64

// scratch (device globals; no allocation allowed)
__device__ float g_q[NB * NR];
__device__ float g_k[NB * NR];
__device__ float g_v[NB * NR];
__device__ float g_rv[NB * NR];

// ---------------------------------------------------------------------------
// Kernel 1: h_t = (1 - sigmoid(alpha_raw)) * h_prev
//                 + tanh(h_prev @ W_w^T + x_t @ U_w^T + U_b)
// NT GEMM, M=8192, N=2048, K=4096 (two 2048 segments), fp32 SIMT.
// BM=BN=128, BK=16, 256 threads, 8x8 per thread (split 4+4), reg prefetch.
// ---------------------------------------------------------------------------
__global__ __launch_bounds__(256, 2)
void k1_liquid(const float* __restrict__ h_prev,
               const float* __restrict__ x_t,
               const float* __restrict__ U_w,
               const float* __restrict__ U_b,
               const float* __restrict__ W_w,
               const float* __restrict__ alpha_raw,
               float* __restrict__ h_t)
{
    __shared__ __align__(16) float As[16][132];
    __shared__ __align__(16) float Ws[16][132];

    const int tid = threadIdx.x;
    const int tx  = tid & 15;
    const int ty  = tid >> 4;
    const int m0  = blockIdx.y * 128;
    const int n0  = blockIdx.x * 128;

    const int lrow = tid >> 2;         // 0..63
    const int lc4  = (tid & 3) << 2;   // 0,4,8,12

    float acc[8][8];
#pragma unroll
    for (int i = 0; i < 8; ++i)
#pragma unroll
        for (int j = 0; j < 8; ++j) acc[i][j] = 0.f;

    const int NT = 256;  // 256 k-tiles of 16 (two segments of 128 tiles each)
    float4 ra0, ra1, rb0, rb1;

    // prefetch tile 0 (segment 0: h_prev / W_w)
    ra0 = *(const float4*)(h_prev + (size_t)(m0 + lrow) * NH + lc4);
    ra1 = *(const float4*)(h_prev + (size_t)(m0 + lrow + 64) * NH + lc4);
    rb0 = *(const float4*)(W_w    + (size_t)(n0 + lrow) * NH + lc4);
    rb1 = *(const float4*)(W_w    + (size_t)(n0 + lrow + 64) * NH + lc4);

    for (int t = 0; t < NT; ++t) {
        __syncthreads();
        As[lc4+0][lrow]    = ra0.x; As[lc4+1][lrow]    = ra0.y;
        As[lc4+2][lrow]    = ra0.z; As[lc4+3][lrow]    = ra0.w;
        As[lc4+0][lrow+64] = ra1.x; As[lc4+1][lrow+64] = ra1.y;
        As[lc4+2][lrow+64] = ra1.z; As[lc4+3][lrow+64] = ra1.w;
        Ws[lc4+0][lrow]    = rb0.x; Ws[lc4+1][lrow]    = rb0.y;
        Ws[lc4+2][lrow]    = rb0.z; Ws[lc4+3][lrow]    = rb0.w;
        Ws[lc4+0][lrow+64] = rb1.x; Ws[lc4+1][lrow+64] = rb1.y;
        Ws[lc4+2][lrow+64] = rb1.z; Ws[lc4+3][lrow+64] = rb1.w;
        __syncthreads();

        if (t + 1 < NT) {
            const int tt = t + 1;
            const float* A = (tt < 128) ? h_prev : x_t;
            const float* W = (tt < 128) ? W_w    : U_w;
            const int k0 = (tt & 127) << 4;
            ra0 = *(const float4*)(A + (size_t)(m0 + lrow) * NH + k0 + lc4);
            ra1 = *(const float4*)(A + (size_t)(m0 + lrow + 64) * NH + k0 + lc4);
            rb0 = *(const float4*)(W + (size_t)(n0 + lrow) * NH + k0 + lc4);
            rb1 = *(const float4*)(W + (size_t)(n0 + lrow + 64) * NH + k0 + lc4);
        }

#pragma unroll
        for (int k = 0; k < 16; ++k) {
            float4 a0 = *(const float4*)&As[k][ty << 2];
            float4 a1 = *(const float4*)&As[k][64 + (ty << 2)];
            float4 b0 = *(const float4*)&Ws[k][tx << 2];
            float4 b1 = *(const float4*)&Ws[k][64 + (tx << 2)];
            float av[8] = {a0.x, a0.y, a0.z, a0.w, a1.x, a1.y, a1.z, a1.w};
            float bv[8] = {b0.x, b0.y, b0.z, b0.w, b1.x, b1.y, b1.z, b1.w};
#pragma unroll
            for (int i = 0; i < 8; ++i)
#pragma unroll
                for (int j = 0; j < 8; ++j)
                    acc[i][j] = fmaf(av[i], bv[j], acc[i][j]);
        }
    }

    // epilogue: per-column bias + (1 - sigmoid(alpha)), per-element tanh + gate
    float omA[8], bias[8];
#pragma unroll
    for (int j = 0; j < 8; ++j) {
        const int c = n0 + ((j < 4) ? ((tx << 2) + j) : (64 + (tx << 2) + j - 4));
        const float ar = alpha_raw[c];
        omA[j]  = 1.f - 1.f / (1.f + expf(-ar));
        bias[j] = U_b[c];
    }
#pragma unroll
    for (int i = 0; i < 8; ++i) {
        const int r = m0 + ((i < 4) ? ((ty << 2) + i) : (64 + (ty << 2) + i - 4));
#pragma unroll
        for (int g = 0; g < 2; ++g) {
            const int c = n0 + g * 64 + (tx << 2);
            float4 hp = *(const float4*)(h_prev + (size_t)r * NH + c);
            float4 o;
            o.x = omA[g*4+0] * hp.x + tanhf(acc[i][g*4+0] + bias[g*4+0]);
            o.y = omA[g*4+1] * hp.y + tanhf(acc[i][g*4+1] + bias[g*4+1]);
            o.z = omA[g*4+2] * hp.z + tanhf(acc[i][g*4+2] + bias[g*4+2]);
            o.w = omA[g*4+3] * hp.w + tanhf(acc[i][g*4+3] + bias[g*4+3]);
            *(float4*)(h_t + (size_t)r * NH + c) = o;
        }
    }
}

// ---------------------------------------------------------------------------
// Kernel 2: q/k/v = h_t @ W{Q,K,V}^T  (M=8192, N=64 per plane, K=2048)
// BM=128, BN=64, BK=16, 256 threads, 8x4 per thread; grid.z selects plane.
// ---------------------------------------------------------------------------
__global__ __launch_bounds__(256, 2)
void k2_qkv(const float* __restrict__ h_t,
            const float* __restrict__ WQ,
            const float* __restrict__ WK,
            const float* __restrict__ WV)
{
    __shared__ __align__(16) float As[16][132];
    __shared__ __align__(16) float Ws[16][68];

    const int tid = threadIdx.x;
    const int tx  = tid & 15;
    const int ty  = tid >> 4;
    const int m0  = blockIdx.x * 128;
    const int z   = blockIdx.z;
    const float* Wm = (z == 0) ? WQ : (z == 1) ? WK : WV;
    float* out      = (z == 0) ? g_q : (z == 1) ? g_k : g_v;

    const int lrow = tid >> 2;        // 0..63
    const int lc4  = (tid & 3) << 2;

    float acc[8][4];
#pragma unroll
    for (int i = 0; i < 8; ++i)
#pragma unroll
        for (int j = 0; j < 4; ++j) acc[i][j] = 0.f;

    const int NT = 128;
    float4 ra0, ra1, rbw;
    ra0 = *(const float4*)(h_t + (size_t)(m0 + lrow) * NH + lc4);
    ra1 = *(const float4*)(h_t + (size_t)(m0 + lrow + 64) * NH + lc4);
    rbw = *(const float4*)(Wm  + (size_t)lrow * NH + lc4);

    for (int t = 0; t < NT; ++t) {
        __syncthreads();
        As[lc4+0][lrow]    = ra0.x; As[lc4+1][lrow]    = ra0.y;
        As[lc4+2][lrow]    = ra0.z; As[lc4+3][lrow]    = ra0.w;
        As[lc4+0][lrow+64] = ra1.x; As[lc4+1][lrow+64] = ra1.y;
        As[lc4+2][lrow+64] = ra1.z; As[lc4+3][lrow+64] = ra1.w;
        Ws[lc4+0][lrow] = rbw.x; Ws[lc4+1][lrow] = rbw.y;
        Ws[lc4+2][lrow] = rbw.z; Ws[lc4+3][lrow] = rbw.w;
        __syncthreads();

        if (t + 1 < NT) {
            const int k0 = (t + 1) << 4;
            ra0 = *(const float4*)(h_t + (size_t)(m0 + lrow) * NH + k0 + lc4);
            ra1 = *(const float4*)(h_t + (size_t)(m0 + lrow + 64) * NH + k0 + lc4);
            rbw = *(const float4*)(Wm  + (size_t)lrow * NH + k0 + lc4);
        }

#pragma unroll
        for (int k = 0; k < 16; ++k) {
            float4 a0 = *(const float4*)&As[k][ty << 2];
            float4 a1 = *(const float4*)&As[k][64 + (ty << 2)];
            float4 b  = *(const float4*)&Ws[k][tx << 2];
            float av[8] = {a0.x, a0.y, a0.z, a0.w, a1.x, a1.y, a1.z, a1.w};
            float bv[4] = {b.x, b.y, b.z, b.w};
#pragma unroll
            for (int i = 0; i < 8; ++i)
#pragma unroll
                for (int j = 0; j < 4; ++j)
                    acc[i][j] = fmaf(av[i], bv[j], acc[i][j]);
        }
    }

#pragma unroll
    for (int i = 0; i < 8; ++i) {
        const int r = m0 + ((i < 4) ? ((ty << 2) + i) : (64 + (ty << 2) + i - 4));
        float4 o = make_float4(acc[i][0], acc[i][1], acc[i][2], acc[i][3]);
        *(float4*)(out + (size_t)r * NR + (tx << 2)) = o;
    }
}

// ---------------------------------------------------------------------------
// Kernel 3: per-row outer-product softmax routing.
// routed_v[b,i] = sum_j softmax_j(q_i * k_j / 8) * v_j.  One warp per row.
// ---------------------------------------------------------------------------
__global__ __launch_bounds__(256)
void k3_attn()
{
    const int warp = (blockIdx.x * blockDim.x + threadIdx.x) >> 5;
    const int lane = threadIdx.x & 31;
    if (warp >= NB) return;

    const float* q = g_q + (size_t)warp * NR;
    const float* k = g_k + (size_t)warp * NR;
    const float* v = g_v + (size_t)warp * NR;

    const float q0 = q[lane], q1 = q[lane + 32];
    const float k0 = k[lane], k1 = k[lane + 32];
    const float v0 = v[lane], v1 = v[lane + 32];

    float out0 = 0.f, out1 = 0.f;
    const unsigned full = 0xffffffffu;

#pragma unroll 4
    for (int i = 0; i < 64; ++i) {
        const float qi = __shfl_sync(full, (i < 32) ? q0 : q1, i & 31);
        const float s0 = qi * k0 * 0.125f;
        const float s1 = qi * k1 * 0.125f;
        float m = fmaxf(s0, s1);
#pragma unroll
        for (int o = 16; o; o >>= 1) m = fmaxf(m, __shfl_xor_sync(full, m, o));
        const float e0 = expf(s0 - m);
        const float e1 = expf(s1 - m);
        float se = e0 + e1;
        float sd = e0 * v0 + e1 * v1;
#pragma unroll
        for (int o = 16; o; o >>= 1) {
            se += __shfl_xor_sync(full, se, o);
            sd += __shfl_xor_sync(full, sd, o);
        }
        const float r = sd / se;
        if ((i & 31) == lane) { if (i < 32) out0 = r; else out1 = r; }
    }

    g_rv[(size_t)warp * NR + lane]      = out0;
    g_rv[(size_t)warp * NR + 32 + lane] = out1;
}

// ---------------------------------------------------------------------------
// Kernel 4: y = gamma * (routed_v @ WO^T) + x_t   (K=64, loaded once to smem)
// BM=32 (batch), BN=128 (h), 256 threads, 4x4 per thread.
// ---------------------------------------------------------------------------
__global__ __launch_bounds__(256)
void k4_out(const float* __restrict__ WO,
            const float* __restrict__ x_t,
            const float* __restrict__ gamma,
            float* __restrict__ y)
{
    __shared__ __align__(16) float RVs[64][36];
    __shared__ __align__(16) float WOs[64][132];

    const int tid = threadIdx.x;
    const int tx  = tid & 31;     // 0..31  -> 4 cols each (128)
    const int ty  = tid >> 5;     // 0..7   -> 4 rows each (32)
    const int m0  = blockIdx.y * 32;
    const int n0  = blockIdx.x * 128;

    // RV tile: 32 rows x 64 k = 512 float4 (2/thread)
#pragma unroll
    for (int i = 0; i < 2; ++i) {
        const int id  = tid + 256 * i;
        const int row = id >> 4;          // 0..31
        const int c4  = (id & 15) << 2;   // 0..60
        float4 vv = *(const float4*)(g_rv + (size_t)(m0 + row) * NR + c4);
        RVs[c4+0][row] = vv.x; RVs[c4+1][row] = vv.y;
        RVs[c4+2][row] = vv.z; RVs[c4+3][row] = vv.w;
    }
    // WO tile: 128 rows x 64 k = 2048 float4 (8/thread)
#pragma unroll
    for (int i = 0; i < 8; ++i) {
        const int id  = tid + 256 * i;
        const int row = id >> 4;          // 0..127
        const int c4  = (id & 15) << 2;
        float4 vv = *(const float4*)(WO + (size_t)(n0 + row) * NR + c4);
        WOs[c4+0][row] = vv.x; WOs[c4+1][row] = vv.y;
        WOs[c4+2][row] = vv.z; WOs[c4+3][row] = vv.w;
    }
    __syncthreads();

    float acc[4][4];
#pragma unroll
    for (int i = 0; i < 4; ++i)
#pragma unroll
        for (int j = 0; j < 4; ++j) acc[i][j] = 0.f;

#pragma unroll
    for (int k = 0; k < 64; ++k) {
        float4 a = *(const float4*)&RVs[k][ty << 2];
        float4 b = *(const float4*)&WOs[k][tx << 2];
        float av[4] = {a.x, a.y, a.z, a.w};
        float bv[4] = {b.x, b.y, b.z, b.w};
#pragma unroll
        for (int i = 0; i < 4; ++i)
#pragma unroll
            for (int j = 0; j < 4; ++j)
                acc[i][j] = fmaf(av[i], bv[j], acc[i][j]);
    }

    const float g = gamma[0];
#pragma unroll
    for (int i = 0; i < 4; ++i) {
        const int r = m0 + (ty << 2) + i;
        const int c = n0 + (tx << 2);
        float4 xv = *(const float4*)(x_t + (size_t)r * NH + c);
        float4 o;
        o.x = g * acc[i][0] + xv.x;
        o.y = g * acc[i][1] + xv.y;
        o.z = g * acc[i][2] + xv.z;
        o.w = g * acc[i][3] + xv.w;
        *(float4*)(y + (size_t)r * NH + c) = o;
    }
}

// ---------------------------------------------------------------------------
extern "C" void kernel_launch(void* const* d_in, const int* in_sizes, int n_in,
                              void* d_out, int out_size)
{
    const float* h_prev    = (const float*)d_in[0];
    const float* x_t       = (const float*)d_in[1];
    const float* U_w       = (const float*)d_in[2];
    const float* U_b       = (const float*)d_in[3];
    const float* W_w       = (const float*)d_in[4];
    const float* alpha_raw = (const float*)d_in[5];
    const float* WQ        = (const float*)d_in[6];
    const float* WK        = (const float*)d_in[7];
    const float* WV        = (const float*)d_in[8];
    const float* WO        = (const float*)d_in[9];
    const float* gamma     = (const float*)d_in[10];

    float* h_t = (float*)d_out;                       // output 0: [B, H]
    float* y_t = h_t + (size_t)NB * NH;               // output 1: [B, H]

    dim3 g1(NH / 128, NB / 128);                      // (16, 64)
    k1_liquid<<<g1, 256>>>(h_prev, x_t, U_w, U_b, W_w, alpha_raw, h_t);

    dim3 g2(NB / 128, 1, 3);                          // (64, 1, 3)
    k2_qkv<<<g2, 256>>>(h_t, WQ, WK, WV);

    k3_attn<<<NB / 8, 256>>>();                       // 8 warps/block

    dim3 g4(NH / 128, NB / 32);                       // (16, 256)
    k4_out<<<g4, 256>>>(WO, x_t, gamma, y_t);
}

// round 3
// speedup vs baseline: 2.4172x; 2.4172x over previous
#include <cuda_runtime.h>
#include <math.h>
#include <stdint.h>

#define NB 8192
#define NH 2048
#define NR 64

// scratch (device globals; no allocation allowed)
__device__ float g_q[NB * NR];
__device__ float g_k[NB * NR];
__device__ float g_v[NB * NR];
__device__ float g_rv[NB * NR];

// ---------------------------------------------------------------------------
// helpers (all sm_80-compatible; NO 'a'-suffix features)
// ---------------------------------------------------------------------------
__device__ __forceinline__ uint32_t smem_u32(const void* p) {
    uint32_t a;
    asm("{ .reg .u64 t; cvta.to.shared.u64 t, %1; cvt.u32.u64 %0, t; }"
        : "=r"(a) : "l"(p));
    return a;
}
__device__ __forceinline__ uint32_t cvt_tf32(uint32_t bits) {
    uint32_t r;
    asm("cvt.rna.tf32.f32 %0, %1;" : "=r"(r) : "f"(__uint_as_float(bits)));
    return r;
}
#define LDMATRIX_X4(r, addr)                                                    \
    asm volatile("ldmatrix.sync.aligned.m8n8.x4.shared.b16 {%0,%1,%2,%3}, [%4];"\
        : "=r"((r)[0]), "=r"((r)[1]), "=r"((r)[2]), "=r"((r)[3]) : "r"(addr))

__device__ __forceinline__ void mma_tf32(float c[4], const uint32_t a[4],
                                         uint32_t b0, uint32_t b1) {
    asm volatile(
        "mma.sync.aligned.m16n8k8.row.col.f32.tf32.tf32.f32 "
        "{%0,%1,%2,%3}, {%4,%5,%6,%7}, {%8,%9}, {%0,%1,%2,%3};"
        : "+f"(c[0]), "+f"(c[1]), "+f"(c[2]), "+f"(c[3])
        : "r"(a[0]), "r"(a[1]), "r"(a[2]), "r"(a[3]), "r"(b0), "r"(b1));
}

#define CP_ASYNC16(saddr, gptr)                                                \
    asm volatile("cp.async.cg.shared.global [%0], [%1], 16;"                   \
        :: "r"(saddr), "l"(gptr) : "memory")
#define CP_COMMIT() asm volatile("cp.async.commit_group;" ::: "memory")
#define CP_WAIT1()  asm volatile("cp.async.wait_group 1;" ::: "memory")

// ---------------------------------------------------------------------------
// Kernel 1 (tf32 mma.sync): h_t = (1-sigmoid(alpha))*h_prev
//                                 + tanh(h_prev@W_w^T + x_t@U_w^T + U_b)
// M(batch)=8192, N(hidden)=2048, K=4096 (two 2048 segments).
// BM=128, BN=256, BK=32, 512 threads (16 warps: 2 x 8), warp tile 64x32.
// 3-stage cp.async pipeline; smem rows 128B with XOR-16B swizzle.
// ---------------------------------------------------------------------------
#define K1_STAGE_BYTES 49152                    // A 16KB + B 32KB
#define K1_SMEM (3 * K1_STAGE_BYTES)            // 144KB

__global__ __launch_bounds__(512, 1)
void k1_liquid_mma(const float* __restrict__ h_prev,
                   const float* __restrict__ x_t,
                   const float* __restrict__ U_w,
                   const float* __restrict__ U_b,
                   const float* __restrict__ W_w,
                   const float* __restrict__ alpha_raw,
                   float* __restrict__ h_t)
{
    extern __shared__ char sm[];
    const uint32_t sbase = smem_u32(sm);

    const int tid  = threadIdx.x;
    const int wid  = tid >> 5;
    const int lane = tid & 31;
    const int warp_m = wid & 1;       // 2 warps over M=128 (64 each)
    const int warp_n = wid >> 1;      // 8 warps over N=256 (32 each)
    const int m0 = blockIdx.y * 128;  // batch tile
    const int n0 = blockIdx.x * 256;  // hidden tile

    // ---- cp.async tile loader: A[128][32f], B[256][32f], swizzled ----
    auto load_stage = [&](int kt, int s) {
        const float* Asrc = (kt < 64) ? h_prev : x_t;
        const float* Bsrc = (kt < 64) ? W_w : U_w;
        const int k0 = (kt & 63) << 5;
        const uint32_t sa = sbase + s * K1_STAGE_BYTES;
        const uint32_t sb = sa + 16384;
#pragma unroll
        for (int i = 0; i < 2; ++i) {             // A: 1024 chunks / 512 thr
            const int id = tid + 512 * i;
            const int row = id >> 3, c = id & 7;
            CP_ASYNC16(sa + row * 128 + (((c ^ (row & 7))) << 4),
                       Asrc + (size_t)(m0 + row) * NH + k0 + c * 4);
        }
#pragma unroll
        for (int i = 0; i < 4; ++i) {             // B: 2048 chunks / 512 thr
            const int id = tid + 512 * i;
            const int row = id >> 3, c = id & 7;
            CP_ASYNC16(sb + row * 128 + (((c ^ (row & 7))) << 4),
                       Bsrc + (size_t)(n0 + row) * NH + k0 + c * 4);
        }
    };

    float acc[4][4][4];
#pragma unroll
    for (int a = 0; a < 4; ++a)
#pragma unroll
        for (int b = 0; b < 4; ++b)
#pragma unroll
            for (int d = 0; d < 4; ++d) acc[a][b][d] = 0.f;

    load_stage(0, 0); CP_COMMIT();
    load_stage(1, 1); CP_COMMIT();

    // ldmatrix per-lane row mapping (standard x4 tiling)
    const int rl   = ((lane >> 3) & 1) * 8 + (lane & 7);  // row within 16
    const int csel = (lane >> 4) & 1;                     // 16B chunk select
    uint32_t aOff[4]; int aSwz[4];
    uint32_t bOff[2]; int bSwz[2];
#pragma unroll
    for (int mt = 0; mt < 4; ++mt) {
        const int r = warp_m * 64 + mt * 16 + rl;
        aOff[mt] = r * 128; aSwz[mt] = r & 7;
    }
#pragma unroll
    for (int p = 0; p < 2; ++p) {
        const int r = warp_n * 32 + p * 16 + rl;
        bOff[p] = 16384 + r * 128; bSwz[p] = r & 7;
    }

    for (int kt = 0; kt < 128; ++kt) {
        const int s = kt % 3;
        CP_WAIT1();
        __syncthreads();
        if (kt + 2 < 128) load_stage(kt + 2, (kt + 2) % 3);
        CP_COMMIT();

        const uint32_t stage = sbase + s * K1_STAGE_BYTES;
#pragma unroll
        for (int ks = 0; ks < 4; ++ks) {
            const int chunk = 2 * ks + csel;
            uint32_t a[4][4], b[2][4];
#pragma unroll
            for (int mt = 0; mt < 4; ++mt)
                LDMATRIX_X4(a[mt], stage + aOff[mt] + ((chunk ^ aSwz[mt]) << 4));
#pragma unroll
            for (int p = 0; p < 2; ++p)
                LDMATRIX_X4(b[p], stage + bOff[p] + ((chunk ^ bSwz[p]) << 4));
#pragma unroll
            for (int mt = 0; mt < 4; ++mt)
#pragma unroll
                for (int j = 0; j < 4; ++j) a[mt][j] = cvt_tf32(a[mt][j]);
#pragma unroll
            for (int p = 0; p < 2; ++p)
#pragma unroll
                for (int j = 0; j < 4; ++j) b[p][j] = cvt_tf32(b[p][j]);
#pragma unroll
            for (int mt = 0; mt < 4; ++mt)
#pragma unroll
                for (int nt = 0; nt < 4; ++nt)
                    mma_tf32(acc[mt][nt], a[mt],
                             b[nt >> 1][nt & 1], b[nt >> 1][2 + (nt & 1)]);
        }
    }

    // ---- epilogue ----
    const int g = lane >> 2, tig = lane & 3;
    const int mBase = m0 + warp_m * 64;
    const int nBase = n0 + warp_n * 32;
#pragma unroll
    for (int nt = 0; nt < 4; ++nt) {
        const int n = nBase + nt * 8 + tig * 2;
        const float om0 = 1.f / (1.f + __expf(alpha_raw[n]));
        const float om1 = 1.f / (1.f + __expf(alpha_raw[n + 1]));
        const float bi0 = U_b[n], bi1 = U_b[n + 1];
#pragma unroll
        for (int mt = 0; mt < 4; ++mt) {
            int m = mBase + mt * 16 + g;
            float2 hp = *(const float2*)(h_prev + (size_t)m * NH + n);
            float2 o;
            o.x = om0 * hp.x + tanhf(acc[mt][nt][0] + bi0);
            o.y = om1 * hp.y + tanhf(acc[mt][nt][1] + bi1);
            *(float2*)(h_t + (size_t)m * NH + n) = o;
            m += 8;
            hp = *(const float2*)(h_prev + (size_t)m * NH + n);
            o.x = om0 * hp.x + tanhf(acc[mt][nt][2] + bi0);
            o.y = om1 * hp.y + tanhf(acc[mt][nt][3] + bi1);
            *(float2*)(h_t + (size_t)m * NH + n) = o;
        }
    }
}

// ---------------------------------------------------------------------------
// Kernel 2 (tf32 mma.sync): q/k/v = h_t @ W{Q,K,V}^T
// M=8192, N=64 (per plane z), K=2048. BM=128, BN=64, BK=32,
// 256 threads (8 warps: 4 x 2), warp tile 32x32, 3-stage cp.async.
// ---------------------------------------------------------------------------
#define K2_STAGE_BYTES 24576                    // A 16KB + B 8KB
#define K2_SMEM (3 * K2_STAGE_BYTES)            // 72KB

__global__ __launch_bounds__(256, 1)
void k2_qkv_mma(const float* __restrict__ h_t,
                const float* __restrict__ WQ,
                const float* __restrict__ WK,
                const float* __restrict__ WV)
{
    extern __shared__ char sm[];
    const uint32_t sbase = smem_u32(sm);

    const int tid  = threadIdx.x;
    const int wid  = tid >> 5;
    const int lane = tid & 31;
    const int warp_m = wid & 3;       // 4 warps over M=128 (32 each)
    const int warp_n = wid >> 2;      // 2 warps over N=64 (32 each)
    const int m0 = blockIdx.x * 128;
    const int z  = blockIdx.z;
    const float* Bsrc = (z == 0) ? WQ : (z == 1) ? WK : WV;
    float* out        = (z == 0) ? g_q : (z == 1) ? g_k : g_v;

    auto load_stage = [&](int kt, int s) {
        const int k0 = kt << 5;
        const uint32_t sa = sbase + s * K2_STAGE_BYTES;
        const uint32_t sb = sa + 16384;
#pragma unroll
        for (int i = 0; i < 4; ++i) {             // A: 1024 chunks / 256 thr
            const int id = tid + 256 * i;
            const int row = id >> 3, c = id & 7;
            CP_ASYNC16(sa + row * 128 + (((c ^ (row & 7))) << 4),
                       h_t + (size_t)(m0 + row) * NH + k0 + c * 4);
        }
#pragma unroll
        for (int i = 0; i < 2; ++i) {             // B: 512 chunks / 256 thr
            const int id = tid + 256 * i;
            const int row = id >> 3, c = id & 7;
            CP_ASYNC16(sb + row * 128 + (((c ^ (row & 7))) << 4),
                       Bsrc + (size_t)row * NH + k0 + c * 4);
        }
    };

    float acc[2][4][4];
#pragma unroll
    for (int a = 0; a < 2; ++a)
#pragma unroll
        for (int b = 0; b < 4; ++b)
#pragma unroll
            for (int d = 0; d < 4; ++d) acc[a][b][d] = 0.f;

    load_stage(0, 0); CP_COMMIT();
    load_stage(1, 1); CP_COMMIT();

    const int rl   = ((lane >> 3) & 1) * 8 + (lane & 7);
    const int csel = (lane >> 4) & 1;
    uint32_t aOff[2]; int aSwz[2];
    uint32_t bOff[2]; int bSwz[2];
#pragma unroll
    for (int mt = 0; mt < 2; ++mt) {
        const int r = warp_m * 32 + mt * 16 + rl;
        aOff[mt] = r * 128; aSwz[mt] = r & 7;
    }
#pragma unroll
    for (int p = 0; p < 2; ++p) {
        const int r = warp_n * 32 + p * 16 + rl;
        bOff[p] = 16384 + r * 128; bSwz[p] = r & 7;
    }

    for (int kt = 0; kt < 64; ++kt) {
        const int s = kt % 3;
        CP_WAIT1();
        __syncthreads();
        if (kt + 2 < 64) load_stage(kt + 2, (kt + 2) % 3);
        CP_COMMIT();

        const uint32_t stage = sbase + s * K2_STAGE_BYTES;
#pragma unroll
        for (int ks = 0; ks < 4; ++ks) {
            const int chunk = 2 * ks + csel;
            uint32_t a[2][4], b[2][4];
#pragma unroll
            for (int mt = 0; mt < 2; ++mt)
                LDMATRIX_X4(a[mt], stage + aOff[mt] + ((chunk ^ aSwz[mt]) << 4));
#pragma unroll
            for (int p = 0; p < 2; ++p)
                LDMATRIX_X4(b[p], stage + bOff[p] + ((chunk ^ bSwz[p]) << 4));
#pragma unroll
            for (int mt = 0; mt < 2; ++mt)
#pragma unroll
                for (int j = 0; j < 4; ++j) a[mt][j] = cvt_tf32(a[mt][j]);
#pragma unroll
            for (int p = 0; p < 2; ++p)
#pragma unroll
                for (int j = 0; j < 4; ++j) b[p][j] = cvt_tf32(b[p][j]);
#pragma unroll
            for (int mt = 0; mt < 2; ++mt)
#pragma unroll
                for (int nt = 0; nt < 4; ++nt)
                    mma_tf32(acc[mt][nt], a[mt],
                             b[nt >> 1][nt & 1], b[nt >> 1][2 + (nt & 1)]);
        }
    }

    const int g = lane >> 2, tig = lane & 3;
    const int mBase = m0 + warp_m * 32;
    const int nBase = warp_n * 32;
#pragma unroll
    for (int nt = 0; nt < 4; ++nt) {
        const int n = nBase + nt * 8 + tig * 2;
#pragma unroll
        for (int mt = 0; mt < 2; ++mt) {
            int m = mBase + mt * 16 + g;
            *(float2*)(out + (size_t)m * NR + n) =
                make_float2(acc[mt][nt][0], acc[mt][nt][1]);
            m += 8;
            *(float2*)(out + (size_t)m * NR + n) =
                make_float2(acc[mt][nt][2], acc[mt][nt][3]);
        }
    }
}

// ---------------------------------------------------------------------------
// Kernel 3: per-row outer-product softmax routing (unchanged, passes)
// ---------------------------------------------------------------------------
__global__ __launch_bounds__(256)
void k3_attn()
{
    const int warp = (blockIdx.x * blockDim.x + threadIdx.x) >> 5;
    const int lane = threadIdx.x & 31;
    if (warp >= NB) return;

    const float* q = g_q + (size_t)warp * NR;
    const float* k = g_k + (size_t)warp * NR;
    const float* v = g_v + (size_t)warp * NR;

    const float q0 = q[lane], q1 = q[lane + 32];
    const float k0 = k[lane], k1 = k[lane + 32];
    const float v0 = v[lane], v1 = v[lane + 32];

    float out0 = 0.f, out1 = 0.f;
    const unsigned full = 0xffffffffu;

#pragma unroll 4
    for (int i = 0; i < 64; ++i) {
        const float qi = __shfl_sync(full, (i < 32) ? q0 : q1, i & 31);
        const float s0 = qi * k0 * 0.125f;
        const float s1 = qi * k1 * 0.125f;
        float m = fmaxf(s0, s1);
#pragma unroll
        for (int o = 16; o; o >>= 1) m = fmaxf(m, __shfl_xor_sync(full, m, o));
        const float e0 = expf(s0 - m);
        const float e1 = expf(s1 - m);
        float se = e0 + e1;
        float sd = e0 * v0 + e1 * v1;
#pragma unroll
        for (int o = 16; o; o >>= 1) {
            se += __shfl_xor_sync(full, se, o);
            sd += __shfl_xor_sync(full, sd, o);
        }
        const float r = sd / se;
        if ((i & 31) == lane) { if (i < 32) out0 = r; else out1 = r; }
    }

    g_rv[(size_t)warp * NR + lane]      = out0;
    g_rv[(size_t)warp * NR + 32 + lane] = out1;
}

// ---------------------------------------------------------------------------
// Kernel 4: y = gamma * (routed_v @ WO^T) + x_t (unchanged, passes)
// ---------------------------------------------------------------------------
__global__ __launch_bounds__(256)
void k4_out(const float* __restrict__ WO,
            const float* __restrict__ x_t,
            const float* __restrict__ gamma,
            float* __restrict__ y)
{
    __shared__ __align__(16) float RVs[64][36];
    __shared__ __align__(16) float WOs[64][132];

    const int tid = threadIdx.x;
    const int tx  = tid & 31;
    const int ty  = tid >> 5;
    const int m0  = blockIdx.y * 32;
    const int n0  = blockIdx.x * 128;

#pragma unroll
    for (int i = 0; i < 2; ++i) {
        const int id  = tid + 256 * i;
        const int row = id >> 4;
        const int c4  = (id & 15) << 2;
        float4 vv = *(const float4*)(g_rv + (size_t)(m0 + row) * NR + c4);
        RVs[c4+0][row] = vv.x; RVs[c4+1][row] = vv.y;
        RVs[c4+2][row] = vv.z; RVs[c4+3][row] = vv.w;
    }
#pragma unroll
    for (int i = 0; i < 8; ++i) {
        const int id  = tid + 256 * i;
        const int row = id >> 4;
        const int c4  = (id & 15) << 2;
        float4 vv = *(const float4*)(WO + (size_t)(n0 + row) * NR + c4);
        WOs[c4+0][row] = vv.x; WOs[c4+1][row] = vv.y;
        WOs[c4+2][row] = vv.z; WOs[c4+3][row] = vv.w;
    }
    __syncthreads();

    float acc[4][4];
#pragma unroll
    for (int i = 0; i < 4; ++i)
#pragma unroll
        for (int j = 0; j < 4; ++j) acc[i][j] = 0.f;

#pragma unroll
    for (int k = 0; k < 64; ++k) {
        float4 a = *(const float4*)&RVs[k][ty << 2];
        float4 b = *(const float4*)&WOs[k][tx << 2];
        float av[4] = {a.x, a.y, a.z, a.w};
        float bv[4] = {b.x, b.y, b.z, b.w};
#pragma unroll
        for (int i = 0; i < 4; ++i)
#pragma unroll
            for (int j = 0; j < 4; ++j)
                acc[i][j] = fmaf(av[i], bv[j], acc[i][j]);
    }

    const float g = gamma[0];
#pragma unroll
    for (int i = 0; i < 4; ++i) {
        const int r = m0 + (ty << 2) + i;
        const int c = n0 + (tx << 2);
        float4 xv = *(const float4*)(x_t + (size_t)r * NH + c);
        float4 o;
        o.x = g * acc[i][0] + xv.x;
        o.y = g * acc[i][1] + xv.y;
        o.z = g * acc[i][2] + xv.z;
        o.w = g * acc[i][3] + xv.w;
        *(float4*)(y + (size_t)r * NH + c) = o;
    }
}

// ---------------------------------------------------------------------------
extern "C" void kernel_launch(void* const* d_in, const int* in_sizes, int n_in,
                              void* d_out, int out_size)
{
    const float* h_prev    = (const float*)d_in[0];
    const float* x_t       = (const float*)d_in[1];
    const float* U_w       = (const float*)d_in[2];
    const float* U_b       = (const float*)d_in[3];
    const float* W_w       = (const float*)d_in[4];
    const float* alpha_raw = (const float*)d_in[5];
    const float* WQ        = (const float*)d_in[6];
    const float* WK        = (const float*)d_in[7];
    const float* WV        = (const float*)d_in[8];
    const float* WO        = (const float*)d_in[9];
    const float* gamma     = (const float*)d_in[10];

    float* h_t = (float*)d_out;                       // output 0: [B, H]
    float* y_t = h_t + (size_t)NB * NH;               // output 1: [B, H]

    cudaFuncSetAttribute(k1_liquid_mma,
                         cudaFuncAttributeMaxDynamicSharedMemorySize, K1_SMEM);
    cudaFuncSetAttribute(k2_qkv_mma,
                         cudaFuncAttributeMaxDynamicSharedMemorySize, K2_SMEM);

    dim3 g1(NH / 256, NB / 128);                      // (8, 64)
    k1_liquid_mma<<<g1, 512, K1_SMEM>>>(h_prev, x_t, U_w, U_b, W_w,
                                        alpha_raw, h_t);

    dim3 g2(NB / 128, 1, 3);                          // (64, 1, 3)
    k2_qkv_mma<<<g2, 256, K2_SMEM>>>(h_t, WQ, WK, WV);

    k3_attn<<<NB / 8, 256>>>();                       // 8 warps/block

    dim3 g4(NH / 128, NB / 32);                       // (16, 256)
    k4_out<<<g4, 256>>>(WO, x_t, gamma, y_t);
}

// round 4
// speedup vs baseline: 5.1010x; 2.1103x over previous
#include <cuda_runtime.h>
#include <cuda_fp16.h>
#include <math.h>
#include <stdint.h>

#define NB 8192
#define NH 2048
#define NR 64

// fp32 scratch
__device__ float g_q[NB * NR];
__device__ float g_k[NB * NR];
__device__ float g_v[NB * NR];
// fp16 scratch
__device__ __half g_hp16[NB * NH];     // h_prev fp16
__device__ __half g_xt16[NB * NH];     // x_t fp16
__device__ __half g_ww16[NH * NH];     // W_w fp16
__device__ __half g_uw16[NH * NH];     // U_w fp16
__device__ __half g_wq16[NR * NH];
__device__ __half g_wk16[NR * NH];
__device__ __half g_wv16[NR * NH];
__device__ __half g_wo16[NH * NR];
__device__ __half g_hth[NB * NH];      // h_t fp16 (k1 epilogue -> k2)
__device__ __half g_rv16[NB * NR];     // routed_v fp16 (k3 -> k4)

// ---------------------------------------------------------------------------
// helpers (sm_80-compatible; NO 'a'-suffix features)
// ---------------------------------------------------------------------------
__device__ __forceinline__ uint32_t smem_u32(const void* p) {
    uint32_t a;
    asm("{ .reg .u64 t; cvta.to.shared.u64 t, %1; cvt.u32.u64 %0, t; }"
        : "=r"(a) : "l"(p));
    return a;
}
#define LDMATRIX_X4(r, addr)                                                    \
    asm volatile("ldmatrix.sync.aligned.m8n8.x4.shared.b16 {%0,%1,%2,%3}, [%4];"\
        : "=r"((r)[0]), "=r"((r)[1]), "=r"((r)[2]), "=r"((r)[3]) : "r"(addr))

__device__ __forceinline__ void mma_f16(float c[4], const uint32_t a[4],
                                        uint32_t b0, uint32_t b1) {
    asm volatile(
        "mma.sync.aligned.m16n8k16.row.col.f32.f16.f16.f32 "
        "{%0,%1,%2,%3}, {%4,%5,%6,%7}, {%8,%9}, {%0,%1,%2,%3};"
        : "+f"(c[0]), "+f"(c[1]), "+f"(c[2]), "+f"(c[3])
        : "r"(a[0]), "r"(a[1]), "r"(a[2]), "r"(a[3]), "r"(b0), "r"(b1));
}

#define CP_ASYNC16(saddr, gptr)                                                \
    asm volatile("cp.async.cg.shared.global [%0], [%1], 16;"                   \
        :: "r"(saddr), "l"(gptr) : "memory")
#define CP_COMMIT() asm volatile("cp.async.commit_group;" ::: "memory")
#define CP_WAIT1()  asm volatile("cp.async.wait_group 1;" ::: "memory")
#define CP_WAIT0()  asm volatile("cp.async.wait_group 0;" ::: "memory")

// ---------------------------------------------------------------------------
// pre-pass: fp32 -> fp16 (RN)
// ---------------------------------------------------------------------------
__global__ void cvt16(const float* __restrict__ src, __half* __restrict__ dst,
                      int n4)
{
    const int i = blockIdx.x * blockDim.x + threadIdx.x;
    if (i < n4) {
        float4 v = ((const float4*)src)[i];
        ((__half2*)dst)[2 * i]     = __floats2half2_rn(v.x, v.y);
        ((__half2*)dst)[2 * i + 1] = __floats2half2_rn(v.z, v.w);
    }
}

// ---------------------------------------------------------------------------
// Kernel 1 (fp16 mma): h_t = (1-sigmoid(alpha))*h_prev
//                            + tanh(h_prev@W_w^T + x_t@U_w^T + U_b)
// M=8192 (batch), N=2048 (hidden), K=4096 (two segments).
// BM=128, BN=256, BK=64, 512 thr (16 warps 2x8), warp tile 64x32,
// 3-stage cp.async, 128B rows w/ XOR-16B swizzle.
// ---------------------------------------------------------------------------
#define K1_STAGE 49152                         // A 16KB + B 32KB
#define K1_SMEM (3 * K1_STAGE)

__global__ __launch_bounds__(512, 1)
void k1_liquid_f16(const float* __restrict__ h_prev,
                   const float* __restrict__ U_b,
                   const float* __restrict__ alpha_raw,
                   float* __restrict__ h_t)
{
    extern __shared__ char sm[];
    const uint32_t sbase = smem_u32(sm);

    const int tid  = threadIdx.x;
    const int wid  = tid >> 5;
    const int lane = tid & 31;
    const int warp_m = wid & 1;
    const int warp_n = wid >> 1;
    const int m0 = blockIdx.y * 128;
    const int n0 = blockIdx.x * 256;

    auto load_stage = [&](int kt, int s) {
        const __half* Asrc = (kt < 32) ? g_hp16 : g_xt16;
        const __half* Bsrc = (kt < 32) ? g_ww16 : g_uw16;
        const int k0 = (kt & 31) << 6;
        const uint32_t sa = sbase + s * K1_STAGE;
        const uint32_t sb = sa + 16384;
#pragma unroll
        for (int i = 0; i < 2; ++i) {            // A: 1024 x 16B / 512 thr
            const int id = tid + 512 * i;
            const int row = id >> 3, c = id & 7;
            CP_ASYNC16(sa + row * 128 + ((c ^ (row & 7)) << 4),
                       Asrc + (size_t)(m0 + row) * NH + k0 + c * 8);
        }
#pragma unroll
        for (int i = 0; i < 4; ++i) {            // B: 2048 x 16B / 512 thr
            const int id = tid + 512 * i;
            const int row = id >> 3, c = id & 7;
            CP_ASYNC16(sb + row * 128 + ((c ^ (row & 7)) << 4),
                       Bsrc + (size_t)(n0 + row) * NH + k0 + c * 8);
        }
    };

    float acc[4][4][4];
#pragma unroll
    for (int a = 0; a < 4; ++a)
#pragma unroll
        for (int b = 0; b < 4; ++b)
#pragma unroll
            for (int d = 0; d < 4; ++d) acc[a][b][d] = 0.f;

    load_stage(0, 0); CP_COMMIT();
    load_stage(1, 1); CP_COMMIT();

    const int rl16 = lane & 15;         // row within 16-row frag
    const int ksel = lane >> 4;         // 16B k-chunk select (0/1)
    uint32_t aOff[4]; int aSwz[4];
    uint32_t bOff[2]; int bSwz[2];
#pragma unroll
    for (int mt = 0; mt < 4; ++mt) {
        const int r = warp_m * 64 + mt * 16 + rl16;
        aOff[mt] = r * 128; aSwz[mt] = r & 7;
    }
#pragma unroll
    for (int p = 0; p < 2; ++p) {
        const int r = warp_n * 32 + p * 16 + rl16;
        bOff[p] = 16384 + r * 128; bSwz[p] = r & 7;
    }

    for (int kt = 0; kt < 64; ++kt) {
        const int s = kt % 3;
        CP_WAIT1();
        __syncthreads();
        if (kt + 2 < 64) load_stage(kt + 2, (kt + 2) % 3);
        CP_COMMIT();

        const uint32_t stage = sbase + s * K1_STAGE;
#pragma unroll
        for (int ks = 0; ks < 4; ++ks) {
            const int chunk = ks * 2 + ksel;
            uint32_t a[4][4], b[2][4];
#pragma unroll
            for (int mt = 0; mt < 4; ++mt)
                LDMATRIX_X4(a[mt], stage + aOff[mt] + ((chunk ^ aSwz[mt]) << 4));
#pragma unroll
            for (int p = 0; p < 2; ++p)
                LDMATRIX_X4(b[p], stage + bOff[p] + ((chunk ^ bSwz[p]) << 4));
#pragma unroll
            for (int mt = 0; mt < 4; ++mt)
#pragma unroll
                for (int nt = 0; nt < 4; ++nt)
                    mma_f16(acc[mt][nt], a[mt],
                            b[nt >> 1][nt & 1], b[nt >> 1][2 + (nt & 1)]);
        }
    }

    // epilogue: fp32 gating + tanh; also emit fp16 h_t copy for k2
    const int g = lane >> 2, tig = lane & 3;
    const int mBase = m0 + warp_m * 64;
    const int nBase = n0 + warp_n * 32;
#pragma unroll
    for (int nt = 0; nt < 4; ++nt) {
        const int n = nBase + nt * 8 + tig * 2;
        const float om0 = 1.f / (1.f + __expf(alpha_raw[n]));
        const float om1 = 1.f / (1.f + __expf(alpha_raw[n + 1]));
        const float bi0 = U_b[n], bi1 = U_b[n + 1];
#pragma unroll
        for (int mt = 0; mt < 4; ++mt) {
            int m = mBase + mt * 16 + g;
            float2 hp = *(const float2*)(h_prev + (size_t)m * NH + n);
            float2 o;
            o.x = om0 * hp.x + tanhf(acc[mt][nt][0] + bi0);
            o.y = om1 * hp.y + tanhf(acc[mt][nt][1] + bi1);
            *(float2*)(h_t + (size_t)m * NH + n) = o;
            *(__half2*)(g_hth + (size_t)m * NH + n) = __floats2half2_rn(o.x, o.y);
            m += 8;
            hp = *(const float2*)(h_prev + (size_t)m * NH + n);
            o.x = om0 * hp.x + tanhf(acc[mt][nt][2] + bi0);
            o.y = om1 * hp.y + tanhf(acc[mt][nt][3] + bi1);
            *(float2*)(h_t + (size_t)m * NH + n) = o;
            *(__half2*)(g_hth + (size_t)m * NH + n) = __floats2half2_rn(o.x, o.y);
        }
    }
}

// ---------------------------------------------------------------------------
// Kernel 2 (fp16 mma): q/k/v = h_t @ W{Q,K,V}^T  (M=8192, N=64, K=2048)
// BM=128, BN=64, BK=64, 256 thr (8 warps 4x2), warp tile 32x32, 3 stages.
// ---------------------------------------------------------------------------
#define K2_STAGE 24576                         // A 16KB + B 8KB
#define K2_SMEM (3 * K2_STAGE)

__global__ __launch_bounds__(256, 1)
void k2_qkv_f16()
{
    extern __shared__ char sm[];
    const uint32_t sbase = smem_u32(sm);

    const int tid  = threadIdx.x;
    const int wid  = tid >> 5;
    const int lane = tid & 31;
    const int warp_m = wid & 3;
    const int warp_n = wid >> 2;
    const int m0 = blockIdx.x * 128;
    const int z  = blockIdx.z;
    const __half* Bsrc = (z == 0) ? g_wq16 : (z == 1) ? g_wk16 : g_wv16;
    float* out         = (z == 0) ? g_q : (z == 1) ? g_k : g_v;

    auto load_stage = [&](int kt, int s) {
        const int k0 = kt << 6;
        const uint32_t sa = sbase + s * K2_STAGE;
        const uint32_t sb = sa + 16384;
#pragma unroll
        for (int i = 0; i < 4; ++i) {            // A: 1024 x 16B / 256 thr
            const int id = tid + 256 * i;
            const int row = id >> 3, c = id & 7;
            CP_ASYNC16(sa + row * 128 + ((c ^ (row & 7)) << 4),
                       g_hth + (size_t)(m0 + row) * NH + k0 + c * 8);
        }
#pragma unroll
        for (int i = 0; i < 2; ++i) {            // B: 512 x 16B / 256 thr
            const int id = tid + 256 * i;
            const int row = id >> 3, c = id & 7;
            CP_ASYNC16(sb + row * 128 + ((c ^ (row & 7)) << 4),
                       Bsrc + (size_t)row * NH + k0 + c * 8);
        }
    };

    float acc[2][4][4];
#pragma unroll
    for (int a = 0; a < 2; ++a)
#pragma unroll
        for (int b = 0; b < 4; ++b)
#pragma unroll
            for (int d = 0; d < 4; ++d) acc[a][b][d] = 0.f;

    load_stage(0, 0); CP_COMMIT();
    load_stage(1, 1); CP_COMMIT();

    const int rl16 = lane & 15;
    const int ksel = lane >> 4;
    uint32_t aOff[2]; int aSwz[2];
    uint32_t bOff[2]; int bSwz[2];
#pragma unroll
    for (int mt = 0; mt < 2; ++mt) {
        const int r = warp_m * 32 + mt * 16 + rl16;
        aOff[mt] = r * 128; aSwz[mt] = r & 7;
    }
#pragma unroll
    for (int p = 0; p < 2; ++p) {
        const int r = warp_n * 32 + p * 16 + rl16;
        bOff[p] = 16384 + r * 128; bSwz[p] = r & 7;
    }

    for (int kt = 0; kt < 32; ++kt) {
        const int s = kt % 3;
        CP_WAIT1();
        __syncthreads();
        if (kt + 2 < 32) load_stage(kt + 2, (kt + 2) % 3);
        CP_COMMIT();

        const uint32_t stage = sbase + s * K2_STAGE;
#pragma unroll
        for (int ks = 0; ks < 4; ++ks) {
            const int chunk = ks * 2 + ksel;
            uint32_t a[2][4], b[2][4];
#pragma unroll
            for (int mt = 0; mt < 2; ++mt)
                LDMATRIX_X4(a[mt], stage + aOff[mt] + ((chunk ^ aSwz[mt]) << 4));
#pragma unroll
            for (int p = 0; p < 2; ++p)
                LDMATRIX_X4(b[p], stage + bOff[p] + ((chunk ^ bSwz[p]) << 4));
#pragma unroll
            for (int mt = 0; mt < 2; ++mt)
#pragma unroll
                for (int nt = 0; nt < 4; ++nt)
                    mma_f16(acc[mt][nt], a[mt],
                            b[nt >> 1][nt & 1], b[nt >> 1][2 + (nt & 1)]);
        }
    }

    const int g = lane >> 2, tig = lane & 3;
    const int mBase = m0 + warp_m * 32;
    const int nBase = warp_n * 32;
#pragma unroll
    for (int nt = 0; nt < 4; ++nt) {
        const int n = nBase + nt * 8 + tig * 2;
#pragma unroll
        for (int mt = 0; mt < 2; ++mt) {
            int m = mBase + mt * 16 + g;
            *(float2*)(out + (size_t)m * NR + n) =
                make_float2(acc[mt][nt][0], acc[mt][nt][1]);
            m += 8;
            *(float2*)(out + (size_t)m * NR + n) =
                make_float2(acc[mt][nt][2], acc[mt][nt][3]);
        }
    }
}

// ---------------------------------------------------------------------------
// Kernel 3: per-row outer-product softmax routing.
// Row max of q_i*k_j is q_i*kmax (q_i>=0) or q_i*kmin: ONE pair of
// reductions replaces 64 per-i trees. Writes fp16 rv for k4.
// ---------------------------------------------------------------------------
__global__ __launch_bounds__(256)
void k3_attn()
{
    const int warp = (blockIdx.x * blockDim.x + threadIdx.x) >> 5;
    const int lane = threadIdx.x & 31;
    if (warp >= NB) return;

    const float* q = g_q + (size_t)warp * NR;
    const float* k = g_k + (size_t)warp * NR;
    const float* v = g_v + (size_t)warp * NR;
    const unsigned full = 0xffffffffu;

    const float q0 = q[lane], q1 = q[lane + 32];
    const float k0 = k[lane], k1 = k[lane + 32];
    const float v0 = v[lane], v1 = v[lane + 32];

    float kmx = fmaxf(k0, k1), kmn = fminf(k0, k1);
#pragma unroll
    for (int o = 16; o; o >>= 1) {
        kmx = fmaxf(kmx, __shfl_xor_sync(full, kmx, o));
        kmn = fminf(kmn, __shfl_xor_sync(full, kmn, o));
    }
    const float m0 = 0.125f * q0 * ((q0 >= 0.f) ? kmx : kmn);
    const float m1 = 0.125f * q1 * ((q1 >= 0.f) ? kmx : kmn);

    float se0 = 0.f, sd0 = 0.f, se1 = 0.f, sd1 = 0.f;
#pragma unroll 8
    for (int j = 0; j < 32; ++j) {
        const float kj = __shfl_sync(full, k0, j);
        const float vj = __shfl_sync(full, v0, j);
        const float e0 = __expf(fmaf(0.125f * q0, kj, -m0));
        const float e1 = __expf(fmaf(0.125f * q1, kj, -m1));
        se0 += e0; sd0 = fmaf(e0, vj, sd0);
        se1 += e1; sd1 = fmaf(e1, vj, sd1);
    }
#pragma unroll 8
    for (int j = 0; j < 32; ++j) {
        const float kj = __shfl_sync(full, k1, j);
        const float vj = __shfl_sync(full, v1, j);
        const float e0 = __expf(fmaf(0.125f * q0, kj, -m0));
        const float e1 = __expf(fmaf(0.125f * q1, kj, -m1));
        se0 += e0; sd0 = fmaf(e0, vj, sd0);
        se1 += e1; sd1 = fmaf(e1, vj, sd1);
    }

    g_rv16[(size_t)warp * NR + lane]      = __float2half(sd0 / se0);
    g_rv16[(size_t)warp * NR + 32 + lane] = __float2half(sd1 / se1);
}

// ---------------------------------------------------------------------------
// Kernel 4 (fp16 mma, single K-shot): y = gamma*(rv @ WO^T) + x_t
// M=8192, N=2048, K=64. BM=128, BN=256, 512 thr (2x8), warp tile 64x32.
// ---------------------------------------------------------------------------
__global__ __launch_bounds__(512, 1)
void k4_out_f16(const float* __restrict__ x_t,
                const float* __restrict__ gamma,
                float* __restrict__ y)
{
    __shared__ __align__(16) char sm4[49152];
    const uint32_t sbase = smem_u32(sm4);

    const int tid  = threadIdx.x;
    const int wid  = tid >> 5;
    const int lane = tid & 31;
    const int warp_m = wid & 1;
    const int warp_n = wid >> 1;
    const int m0 = blockIdx.y * 128;
    const int n0 = blockIdx.x * 256;

    // A: rv tile 128 x 64 halfs (128B rows); B: WO tile 256 x 64 halfs
#pragma unroll
    for (int i = 0; i < 2; ++i) {
        const int id = tid + 512 * i;
        const int row = id >> 3, c = id & 7;
        CP_ASYNC16(sbase + row * 128 + ((c ^ (row & 7)) << 4),
                   g_rv16 + (size_t)(m0 + row) * NR + c * 8);
    }
#pragma unroll
    for (int i = 0; i < 4; ++i) {
        const int id = tid + 512 * i;
        const int row = id >> 3, c = id & 7;
        CP_ASYNC16(sbase + 16384 + row * 128 + ((c ^ (row & 7)) << 4),
                   g_wo16 + (size_t)(n0 + row) * NR + c * 8);
    }
    CP_COMMIT(); CP_WAIT0();
    __syncthreads();

    const int rl16 = lane & 15;
    const int ksel = lane >> 4;
    float acc[4][4][4];
#pragma unroll
    for (int a = 0; a < 4; ++a)
#pragma unroll
        for (int b = 0; b < 4; ++b)
#pragma unroll
            for (int d = 0; d < 4; ++d) acc[a][b][d] = 0.f;

#pragma unroll
    for (int ks = 0; ks < 4; ++ks) {
        const int chunk = ks * 2 + ksel;
        uint32_t a[4][4], b[2][4];
#pragma unroll
        for (int mt = 0; mt < 4; ++mt) {
            const int r = warp_m * 64 + mt * 16 + rl16;
            LDMATRIX_X4(a[mt], sbase + r * 128 + ((chunk ^ (r & 7)) << 4));
        }
#pragma unroll
        for (int p = 0; p < 2; ++p) {
            const int r = warp_n * 32 + p * 16 + rl16;
            LDMATRIX_X4(b[p], sbase + 16384 + r * 128 + ((chunk ^ (r & 7)) << 4));
        }
#pragma unroll
        for (int mt = 0; mt < 4; ++mt)
#pragma unroll
            for (int nt = 0; nt < 4; ++nt)
                mma_f16(acc[mt][nt], a[mt],
                        b[nt >> 1][nt & 1], b[nt >> 1][2 + (nt & 1)]);
    }

    const float gm = gamma[0];
    const int g = lane >> 2, tig = lane & 3;
    const int mBase = m0 + warp_m * 64;
    const int nBase = n0 + warp_n * 32;
#pragma unroll
    for (int nt = 0; nt < 4; ++nt) {
        const int n = nBase + nt * 8 + tig * 2;
#pragma unroll
        for (int mt = 0; mt < 4; ++mt) {
            int m = mBase + mt * 16 + g;
            float2 xv = *(const float2*)(x_t + (size_t)m * NH + n);
            float2 o;
            o.x = fmaf(gm, acc[mt][nt][0], xv.x);
            o.y = fmaf(gm, acc[mt][nt][1], xv.y);
            *(float2*)(y + (size_t)m * NH + n) = o;
            m += 8;
            xv = *(const float2*)(x_t + (size_t)m * NH + n);
            o.x = fmaf(gm, acc[mt][nt][2], xv.x);
            o.y = fmaf(gm, acc[mt][nt][3], xv.y);
            *(float2*)(y + (size_t)m * NH + n) = o;
        }
    }
}

// ---------------------------------------------------------------------------
extern "C" void kernel_launch(void* const* d_in, const int* in_sizes, int n_in,
                              void* d_out, int out_size)
{
    const float* h_prev    = (const float*)d_in[0];
    const float* x_t       = (const float*)d_in[1];
    const float* U_w       = (const float*)d_in[2];
    const float* U_b       = (const float*)d_in[3];
    const float* W_w       = (const float*)d_in[4];
    const float* alpha_raw = (const float*)d_in[5];
    const float* WQ        = (const float*)d_in[6];
    const float* WK        = (const float*)d_in[7];
    const float* WV        = (const float*)d_in[8];
    const float* WO        = (const float*)d_in[9];
    const float* gamma     = (const float*)d_in[10];

    float* h_t = (float*)d_out;
    float* y_t = h_t + (size_t)NB * NH;

    cudaFuncSetAttribute(k1_liquid_f16,
                         cudaFuncAttributeMaxDynamicSharedMemorySize, K1_SMEM);
    cudaFuncSetAttribute(k2_qkv_f16,
                         cudaFuncAttributeMaxDynamicSharedMemorySize, K2_SMEM);

    __half *d_hp16, *d_xt16, *d_ww16, *d_uw16, *d_wq16, *d_wk16, *d_wv16, *d_wo16;
    cudaGetSymbolAddress((void**)&d_hp16, g_hp16);
    cudaGetSymbolAddress((void**)&d_xt16, g_xt16);
    cudaGetSymbolAddress((void**)&d_ww16, g_ww16);
    cudaGetSymbolAddress((void**)&d_uw16, g_uw16);
    cudaGetSymbolAddress((void**)&d_wq16, g_wq16);
    cudaGetSymbolAddress((void**)&d_wk16, g_wk16);
    cudaGetSymbolAddress((void**)&d_wv16, g_wv16);
    cudaGetSymbolAddress((void**)&d_wo16, g_wo16);

    const int big4 = NB * NH / 4;          // 4,194,304
    const int ww4  = NH * NH / 4;          // 1,048,576
    const int w64  = NR * NH / 4;          // 32,768
    cvt16<<<(big4 + 255) / 256, 256>>>(h_prev, d_hp16, big4);
    cvt16<<<(big4 + 255) / 256, 256>>>(x_t,    d_xt16, big4);
    cvt16<<<(ww4 + 255) / 256, 256>>>(W_w,     d_ww16, ww4);
    cvt16<<<(ww4 + 255) / 256, 256>>>(U_w,     d_uw16, ww4);
    cvt16<<<(w64 + 255) / 256, 256>>>(WQ,      d_wq16, w64);
    cvt16<<<(w64 + 255) / 256, 256>>>(WK,      d_wk16, w64);
    cvt16<<<(w64 + 255) / 256, 256>>>(WV,      d_wv16, w64);
    cvt16<<<(w64 + 255) / 256, 256>>>(WO,      d_wo16, w64);

    dim3 g1(NH / 256, NB / 128);                      // (8, 64)
    k1_liquid_f16<<<g1, 512, K1_SMEM>>>(h_prev, U_b, alpha_raw, h_t);

    dim3 g2(NB / 128, 1, 3);                          // (64, 1, 3)
    k2_qkv_f16<<<g2, 256, K2_SMEM>>>();

    k3_attn<<<NB / 8, 256>>>();

    dim3 g4(NH / 256, NB / 128);                      // (8, 64)
    k4_out_f16<<<g4, 512>>>(x_t, gamma, y_t);
}